// round 5
// baseline (speedup 1.0000x reference)
#include <cuda_runtime.h>
#include <cuda_fp16.h>
#include <cstdint>

// ---------------------------------------------------------------------------
// GCN, 4 layers + heads. R5:
//  - activations g_hs stored fp16 (halves L2 gather traffic), fp32 accumulate
//  - layers 0-2: agg (gather CSR) -> tensor-core GEMM (mma.sync tf32)
//  - layer 3 + PI/V heads collapsed algebraically
//  - small setup kernels merged (norm+prep into scan; scale0 into fill)
// ---------------------------------------------------------------------------

constexpr int NN = 50000;
constexpr int NE = 800000;

__device__ int      g_outdeg[NN];
__device__ int      g_indeg[NN];
__device__ float    g_nsrc[NN];
__device__ float    g_ndst[NN];
__device__ int      g_rowptr[NN + 1];
__device__ int      g_cursor[NN];
__device__ int      g_esrc[NE];
__device__ uint2    g_hs[(size_t)NN * 32];   // fp16 activations: 32 uint2 = 128 halves/node
__device__ float    g_agg[(size_t)NN * 128]; // aggregated * norm_dst (GEMM input, fp32)
__device__ float2   g_zz[NN];                // (z, z2) per node
__device__ float    g_q[128];                // W3 @ Wp
__device__ float    g_q2[128];               // W3 @ Wv
__device__ float    g_cPI;

__device__ __forceinline__ uint32_t f2tf32(float x) {
    uint32_t r; asm("cvt.rna.tf32.f32 %0, %1;" : "=r"(r) : "f"(x)); return r;
}

__device__ __forceinline__ void mma_tf32(float* c, const uint32_t* a,
                                         uint32_t b0, uint32_t b1) {
    asm("mma.sync.aligned.m16n8k8.row.col.f32.tf32.tf32.f32 "
        "{%0,%1,%2,%3},{%4,%5,%6,%7},{%8,%9},{%0,%1,%2,%3};"
        : "+f"(c[0]), "+f"(c[1]), "+f"(c[2]), "+f"(c[3])
        : "r"(a[0]), "r"(a[1]), "r"(a[2]), "r"(a[3]), "r"(b0), "r"(b1));
}

__device__ __forceinline__ uint2 pack4h(float4 v) {
    uint2 r;
    __half2 h0 = __floats2half2_rn(v.x, v.y);
    __half2 h1 = __floats2half2_rn(v.z, v.w);
    r.x = *(uint32_t*)&h0;
    r.y = *(uint32_t*)&h1;
    return r;
}
__device__ __forceinline__ float4 unpack4h(uint2 u) {
    __half2 h0 = *(__half2*)&u.x;
    __half2 h1 = *(__half2*)&u.y;
    float2 f0 = __half22float2(h0);
    float2 f1 = __half22float2(h1);
    return make_float4(f0.x, f0.y, f1.x, f1.y);
}

// --------------------------- setup ----------------------------------------

__global__ void k_zero() {
    int i = blockIdx.x * blockDim.x + threadIdx.x;
    if (i < NN) { g_outdeg[i] = 0; g_indeg[i] = 0; }
}

__global__ void k_hist(const int* __restrict__ src, const int* __restrict__ dst) {
    int e = blockIdx.x * blockDim.x + threadIdx.x;
    if (e < NE) {
        atomicAdd(&g_outdeg[src[e]], 1);
        atomicAdd(&g_indeg[dst[e]], 1);
    }
}

// Single-block: scan in-degrees -> rowptr/cursor, compute norms, head prep.
__global__ void k_scan(const float* __restrict__ W3, const float* __restrict__ b3,
                       const float* __restrict__ Wp, const float* __restrict__ bp,
                       const float* __restrict__ Wv, const float* __restrict__ bv,
                       float* __restrict__ out) {
    constexpr int CH = (NN + 1023) / 1024;   // 49
    __shared__ int ts[1024];
    int t = threadIdx.x;
    int base = t * CH;
    int s = 0;
    for (int i = 0; i < CH; i++) {
        int idx = base + i;
        int v = (idx < NN) ? g_indeg[idx] : 0;
        if (idx < NN) g_rowptr[idx] = s;
        s += v;
    }
    ts[t] = s;
    __syncthreads();
    for (int off = 1; off < 1024; off <<= 1) {
        int v = (t >= off) ? ts[t - off] : 0;
        __syncthreads();
        ts[t] += v;
        __syncthreads();
    }
    int offset = ts[t] - s;
    for (int i = 0; i < CH; i++) {
        int idx = base + i;
        if (idx < NN) {
            int p = g_rowptr[idx] + offset;
            g_rowptr[idx] = p;
            g_cursor[idx] = p;
            g_nsrc[idx] = rsqrtf((float)max(g_outdeg[idx], 1));
            g_ndst[idx] = rsqrtf((float)max(g_indeg[idx], 1));
        }
    }
    if (t == 1023) g_rowptr[NN] = ts[1023];

    // head precompute: q = W3@Wp, q2 = W3@Wv, constants
    if (t < 128) {
        float a = 0.f, c = 0.f;
        for (int j = 0; j < 64; j++) {
            float w = W3[t * 64 + j];
            a += w * Wp[j];
            c += w * Wv[j];
        }
        g_q[t] = a;
        g_q2[t] = c;
        if (t == 0) {
            float cp = 0.f, cv = 0.f;
            for (int j = 0; j < 64; j++) { cp += b3[j] * Wp[j]; cv += b3[j] * Wv[j]; }
            g_cPI = cp + bp[0];
            out[NN] = (float)NN * cv + bv[0];
        }
    }
}

// fill CSR + scale features to fp16 hs, one kernel (disjoint index ranges)
__global__ void k_fillscale(const int* __restrict__ src, const int* __restrict__ dst,
                            const float* __restrict__ feats) {
    int i = blockIdx.x * blockDim.x + threadIdx.x;
    if (i < NE) {
        int p = atomicAdd(&g_cursor[dst[i]], 1);
        g_esrc[p] = src[i];
    } else {
        int j = i - NE;                    // 0 .. NN*32-1
        if (j < NN * 32) {
            int node = j >> 5;
            float s = g_nsrc[node];
            float4 x = ((const float4*)feats)[j];
            x.x *= s; x.y *= s; x.z *= s; x.w *= s;
            g_hs[j] = pack4h(x);
        }
    }
}

// --------------------------- aggregation ----------------------------------
// One warp per node; lane owns 4 feats (8B). 8-deep edge unroll for MLP.

__global__ void k_agg() {
    int v = blockIdx.x * (blockDim.x >> 5) + (threadIdx.x >> 5);
    if (v >= NN) return;
    int lane = threadIdx.x & 31;
    int beg = g_rowptr[v], end = g_rowptr[v + 1];
    float4 a0 = make_float4(0.f, 0.f, 0.f, 0.f);
    float4 a1 = a0;
    int e = beg;
    for (; e + 7 < end; e += 8) {
        uint2 x[8];
        #pragma unroll
        for (int j = 0; j < 8; j++)
            x[j] = g_hs[(size_t)g_esrc[e + j] * 32 + lane];
        #pragma unroll
        for (int j = 0; j < 8; j += 2) {
            float4 f0 = unpack4h(x[j]);
            float4 f1 = unpack4h(x[j + 1]);
            a0.x += f0.x; a0.y += f0.y; a0.z += f0.z; a0.w += f0.w;
            a1.x += f1.x; a1.y += f1.y; a1.z += f1.z; a1.w += f1.w;
        }
    }
    for (; e < end; e++) {
        float4 f = unpack4h(g_hs[(size_t)g_esrc[e] * 32 + lane]);
        a0.x += f.x; a0.y += f.y; a0.z += f.z; a0.w += f.w;
    }
    float nd = g_ndst[v];
    float4 o;
    o.x = (a0.x + a1.x) * nd;
    o.y = (a0.y + a1.y) * nd;
    o.z = (a0.z + a1.z) * nd;
    o.w = (a0.w + a1.w) * nd;
    ((float4*)g_agg)[v * 32 + lane] = o;
}

// --------------------------- tensor-core GEMM ------------------------------
// g_hs = fp16(relu(g_agg @ W + b) * nsrc); W 128x128 row-major [k][n].
// Block: 128 rows x 128 cols, 256 threads. mma.sync m16n8k8 tf32.

constexpr int PADA = 132;
constexpr int PADW = 136;
constexpr int GEMM_SMEM = (128 * PADA + 128 * PADW) * 4;   // 137216 B

__global__ void __launch_bounds__(256) k_gemm(const float* __restrict__ W,
                                              const float* __restrict__ b) {
    extern __shared__ uint32_t sm[];
    uint32_t* sA = sm;                 // [row][k] tf32 bits, stride PADA
    uint32_t* sW = sm + 128 * PADA;    // [k][n]  tf32 bits, stride PADW

    int tid  = threadIdx.x;
    int lane = tid & 31;
    int warp = tid >> 5;
    int row0 = blockIdx.x * 128;

    const float4* A4 = (const float4*)g_agg;
    #pragma unroll
    for (int it = 0; it < 16; it++) {
        int i  = it * 256 + tid;
        int r  = i >> 5;
        int c4 = i & 31;
        int gr = row0 + r;
        float4 v = (gr < NN) ? A4[gr * 32 + c4] : make_float4(0.f, 0.f, 0.f, 0.f);
        uint4 t = make_uint4(f2tf32(v.x), f2tf32(v.y), f2tf32(v.z), f2tf32(v.w));
        *(uint4*)&sA[r * PADA + c4 * 4] = t;
    }
    const float4* W4 = (const float4*)W;
    #pragma unroll
    for (int it = 0; it < 16; it++) {
        int i  = it * 256 + tid;
        int k  = i >> 5;
        int c4 = i & 31;
        float4 v = W4[k * 32 + c4];
        uint4 t = make_uint4(f2tf32(v.x), f2tf32(v.y), f2tf32(v.z), f2tf32(v.w));
        *(uint4*)&sW[k * PADW + c4 * 4] = t;
    }
    __syncthreads();

    int wm = (warp >> 1) * 32;
    int wn = (warp & 1) * 64;

    float acc[2][8][4];
    #pragma unroll
    for (int mf = 0; mf < 2; mf++)
        #pragma unroll
        for (int nf = 0; nf < 8; nf++)
            #pragma unroll
            for (int j = 0; j < 4; j++) acc[mf][nf][j] = 0.f;

    int qr = lane >> 2;
    int qc = lane & 3;

    #pragma unroll
    for (int ks = 0; ks < 16; ks++) {
        int kb = ks * 8;
        uint32_t a[2][4];
        #pragma unroll
        for (int mf = 0; mf < 2; mf++) {
            int r = wm + mf * 16 + qr;
            a[mf][0] = sA[r * PADA + kb + qc];
            a[mf][1] = sA[(r + 8) * PADA + kb + qc];
            a[mf][2] = sA[r * PADA + kb + qc + 4];
            a[mf][3] = sA[(r + 8) * PADA + kb + qc + 4];
        }
        #pragma unroll
        for (int nf = 0; nf < 8; nf++) {
            int n = wn + nf * 8 + qr;
            uint32_t b0 = sW[(kb + qc) * PADW + n];
            uint32_t b1 = sW[(kb + qc + 4) * PADW + n];
            mma_tf32(acc[0][nf], a[0], b0, b1);
            mma_tf32(acc[1][nf], a[1], b0, b1);
        }
    }

    // epilogue: bias + relu + nsrc scale -> fp16 hs
    #pragma unroll
    for (int mf = 0; mf < 2; mf++) {
        int r0 = row0 + wm + mf * 16 + qr;
        int r1 = r0 + 8;
        float s0 = (r0 < NN) ? g_nsrc[r0] : 0.f;
        float s1 = (r1 < NN) ? g_nsrc[r1] : 0.f;
        #pragma unroll
        for (int nf = 0; nf < 8; nf++) {
            int c = wn + nf * 8 + qc * 2;
            float2 bb = *(const float2*)&b[c];
            if (r0 < NN) {
                __half2 h = __floats2half2_rn(
                    fmaxf(acc[mf][nf][0] + bb.x, 0.f) * s0,
                    fmaxf(acc[mf][nf][1] + bb.y, 0.f) * s0);
                ((__half2*)g_hs)[(size_t)r0 * 64 + (c >> 1)] = h;
            }
            if (r1 < NN) {
                __half2 h = __floats2half2_rn(
                    fmaxf(acc[mf][nf][2] + bb.x, 0.f) * s1,
                    fmaxf(acc[mf][nf][3] + bb.y, 0.f) * s1);
                ((__half2*)g_hs)[(size_t)r1 * 64 + (c >> 1)] = h;
            }
        }
    }
}

// ---------------------- collapsed layer 3 + heads --------------------------

__global__ void k_z() {
    int v = blockIdx.x * (blockDim.x >> 5) + (threadIdx.x >> 5);
    if (v >= NN) return;
    int lane = threadIdx.x & 31;
    float4 h = unpack4h(g_hs[(size_t)v * 32 + lane]);
    float4 q = ((const float4*)g_q)[lane];
    float4 q2 = ((const float4*)g_q2)[lane];
    float z  = h.x * q.x  + h.y * q.y  + h.z * q.z  + h.w * q.w;
    float z2 = h.x * q2.x + h.y * q2.y + h.z * q2.z + h.w * q2.w;
    #pragma unroll
    for (int off = 16; off; off >>= 1) {
        z  += __shfl_xor_sync(0xffffffff, z,  off);
        z2 += __shfl_xor_sync(0xffffffff, z2, off);
    }
    if (lane == 0) g_zz[v] = make_float2(z, z2);
}

__global__ void k_zagg(float* __restrict__ out) {
    __shared__ float red[256];
    int v = blockIdx.x * blockDim.x + threadIdx.x;
    float vp = 0.f;
    if (v < NN) {
        int beg = g_rowptr[v], end = g_rowptr[v + 1];
        float s0 = 0.f, s1 = 0.f, t0 = 0.f, t1 = 0.f;
        int e = beg;
        for (; e + 1 < end; e += 2) {
            float2 a = g_zz[g_esrc[e]];
            float2 b = g_zz[g_esrc[e + 1]];
            s0 += a.x; t0 += a.y;
            s1 += b.x; t1 += b.y;
        }
        if (e < end) {
            float2 a = g_zz[g_esrc[e]];
            s0 += a.x; t0 += a.y;
        }
        float nd = g_ndst[v];
        out[v] = nd * (s0 + s1) + g_cPI;
        vp = nd * (t0 + t1);
    }
    red[threadIdx.x] = vp;
    __syncthreads();
    for (int off = 128; off; off >>= 1) {
        if (threadIdx.x < off) red[threadIdx.x] += red[threadIdx.x + off];
        __syncthreads();
    }
    if (threadIdx.x == 0) atomicAdd(&out[NN], red[0]);
}

// --------------------------- launch ----------------------------------------

extern "C" void kernel_launch(void* const* d_in, const int* in_sizes, int n_in,
                              void* d_out, int out_size) {
    const float* feats = (const float*)d_in[0];
    const int*   src   = (const int*)d_in[1];
    const int*   dst   = (const int*)d_in[2];
    const float* W0 = (const float*)d_in[3];  const float* b0 = (const float*)d_in[4];
    const float* W1 = (const float*)d_in[5];  const float* b1 = (const float*)d_in[6];
    const float* W2 = (const float*)d_in[7];  const float* b2 = (const float*)d_in[8];
    const float* W3 = (const float*)d_in[9];  const float* b3 = (const float*)d_in[10];
    const float* Wp = (const float*)d_in[11]; const float* bp = (const float*)d_in[12];
    const float* Wv = (const float*)d_in[13]; const float* bv = (const float*)d_in[14];
    float* out = (float*)d_out;

    cudaFuncSetAttribute(k_gemm, cudaFuncAttributeMaxDynamicSharedMemorySize,
                         GEMM_SMEM);

    k_zero<<<(NN + 255) / 256, 256>>>();
    k_hist<<<(NE + 255) / 256, 256>>>(src, dst);
    k_scan<<<1, 1024>>>(W3, b3, Wp, bp, Wv, bv, out);
    k_fillscale<<<(NE + NN * 32 + 255) / 256, 256>>>(src, dst, feats);

    const int aggGrid  = (NN + 7) / 8;        // 8 warps/block
    const int gemmGrid = (NN + 127) / 128;    // 391

    k_agg<<<aggGrid, 256>>>();
    k_gemm<<<gemmGrid, 256, GEMM_SMEM>>>(W0, b0);
    k_agg<<<aggGrid, 256>>>();
    k_gemm<<<gemmGrid, 256, GEMM_SMEM>>>(W1, b1);
    k_agg<<<aggGrid, 256>>>();
    k_gemm<<<gemmGrid, 256, GEMM_SMEM>>>(W2, b2);

    k_z<<<aggGrid, 256>>>();
    k_zagg<<<(NN + 255) / 256, 256>>>(out);
}